// round 16
// baseline (speedup 1.0000x reference)
#include <cuda_runtime.h>
#include <math.h>

#define BB   4
#define SS   2048
#define HH   8
#define DHH  32
#define DIMM 256
#define NB   512          // SS / 4 compressed blocks
#define BS   (BB*SS)      // 8192 rows
#define BSD  (BS*DIMM)    // 2097152 floats
#define QT3  64           // queries per attn block
#define NQT3 (SS/QT3)     // 32 qtiles
#define TN   16           // kv-tile width (pooled blocks)

typedef unsigned long long ull;

// ---------------- scratch (static device buffers; no allocs) ----------------
__device__ float g_h  [BSD];
__device__ float g_q  [BSD];
__device__ float g_k  [BSD];
__device__ float g_v  [BSD];
__device__ float g_o  [BSD];
__device__ float g_g  [BS*24];
__device__ float g_kch[BB*HH*NB*DHH];   // pooled K, tf32 hi
__device__ float g_kcl[BB*HH*NB*DHH];   // pooled K, tf32 lo (residual)
__device__ float g_vc [BB*HH*NB*DHH];   // pooled V, fp32
__device__ float g_mid[BS*512];

__device__ __forceinline__ void cp_async16(void* smem, const void* gmem) {
    unsigned saddr = (unsigned)__cvta_generic_to_shared(smem);
    asm volatile("cp.async.ca.shared.global [%0], [%1], 16;\n" :: "r"(saddr), "l"(gmem));
}
#define CP_COMMIT() asm volatile("cp.async.commit_group;\n" ::: "memory")
#define CP_WAIT0()  asm volatile("cp.async.wait_group 0;\n" ::: "memory")

__device__ __forceinline__ unsigned f2tf32(float x) {
    unsigned u; asm("cvt.rna.tf32.f32 %0, %1;" : "=r"(u) : "f"(x)); return u;
}

__device__ __forceinline__ void mma_tf32(float* c, const unsigned* a, const unsigned* b) {
    asm volatile(
        "mma.sync.aligned.m16n8k8.row.col.f32.tf32.tf32.f32 "
        "{%0,%1,%2,%3}, {%4,%5,%6,%7}, {%8,%9}, {%0,%1,%2,%3};"
        : "+f"(c[0]), "+f"(c[1]), "+f"(c[2]), "+f"(c[3])
        : "r"(a[0]), "r"(a[1]), "r"(a[2]), "r"(a[3]), "r"(b[0]), "r"(b[1]));
}

// ---------------- packed f32x2 helpers ----------------
__device__ __forceinline__ ull pk2(float lo, float hi) {
    ull r; asm("mov.b64 %0, {%1,%2};" : "=l"(r) : "f"(lo), "f"(hi)); return r;
}
__device__ __forceinline__ void upk2(float& lo, float& hi, ull v) {
    asm("mov.b64 {%0,%1}, %2;" : "=f"(lo), "=f"(hi) : "l"(v));
}
__device__ __forceinline__ ull fma2(ull a, ull b, ull c) {
    ull d; asm("fma.rn.f32x2 %0, %1, %2, %3;" : "=l"(d) : "l"(a), "l"(b), "l"(c)); return d;
}
__device__ __forceinline__ ull mul2(ull a, ull b) {
    ull d; asm("mul.rn.f32x2 %0, %1, %2;" : "=l"(d) : "l"(a), "l"(b)); return d;
}
__device__ __forceinline__ float ex2(float x) {
    float y; asm("ex2.approx.f32 %0, %1;" : "=f"(y) : "f"(x)); return y;
}

// ---------------- LayerNorm: one warp per row of 256 ----------------
__global__ void ln_kernel(const float* __restrict__ x, const float* __restrict__ gw,
                          const float* __restrict__ bw, float* __restrict__ out)
{
    int warp = (blockIdx.x * blockDim.x + threadIdx.x) >> 5;
    int lane = threadIdx.x & 31;
    if (warp >= BS) return;
    const float* xr = x + (size_t)warp * DIMM;
    float vbuf[8];
    float s = 0.f;
    #pragma unroll
    for (int i = 0; i < 8; i++) { vbuf[i] = xr[lane + i*32]; s += vbuf[i]; }
    #pragma unroll
    for (int o = 16; o > 0; o >>= 1) s += __shfl_xor_sync(~0u, s, o);
    float m = s * (1.f/256.f);
    float sq = 0.f;
    #pragma unroll
    for (int i = 0; i < 8; i++) { float d = vbuf[i] - m; sq += d*d; }
    #pragma unroll
    for (int o = 16; o > 0; o >>= 1) sq += __shfl_xor_sync(~0u, sq, o);
    float rstd = rsqrtf(sq * (1.f/256.f) + 1e-5f);
    float* orow = out + (size_t)warp * DIMM;
    #pragma unroll
    for (int i = 0; i < 8; i++) {
        int c = lane + i*32;
        orow[c] = (vbuf[i] - m) * rstd * gw[c] + bw[c];
    }
}

// ---------------- main GEMM: 3xTF32 tensor-core, 128x128 tile, BK=16 --------
#define AH_(b,r,c) sAh[((b)*128 + (r))*20 + (c)]
#define AL_(b,r,c) sAl[((b)*128 + (r))*20 + (c)]
#define BH_(b,k,c) sBh[((b)*16  + (k))*136 + (c)]
#define BL_(b,k,c) sBl[((b)*16  + (k))*136 + (c)]
#define GEMM_SMEM_BYTES ((2*128*20*2 + 2*16*136*2) * 4)

template<int EPI, bool QKV>
__global__ void __launch_bounds__(256, 2) mma_gemm_kernel(
    const float* __restrict__ A,
    const float* __restrict__ B0, const float* __restrict__ B1,
    const float* __restrict__ B2, const float* __restrict__ B3,
    const float* __restrict__ bias,
    float* __restrict__ C0, float* __restrict__ C1,
    float* __restrict__ C2, float* __restrict__ C3,
    int M, int N, int K)
{
    extern __shared__ float sm_[];
    float* sAh = sm_;
    float* sAl = sAh + 2*128*20;
    float* sBh = sAl + 2*128*20;
    float* sBl = sBh + 2*16*136;

    const float* B = B0;
    float* C = C0;
    int Nn = N;
    bool gate = false;
    if (QKV) {
        if (blockIdx.z == 1)      { B = B1; C = C1; }
        else if (blockIdx.z == 2) { B = B2; C = C2; }
        else if (blockIdx.z == 3) {
            if (blockIdx.x > 0) return;
            B = B3; C = C3; Nn = 24; gate = true;
        }
    }

    int tid  = threadIdx.x;
    int wid  = tid >> 5, lane = tid & 31;
    int g    = lane >> 2, tg = lane & 3;
    int wm   = (wid >> 2) << 6;
    int wn   = (wid & 3) << 5;
    int bm   = blockIdx.y << 7, bn = blockIdx.x << 7;

    int ar  = tid >> 2, akq = tid & 3;
    const float* Ap0 = A + (size_t)(bm + ar)*K + (akq << 2);
    const float* Ap1 = A + (size_t)(bm + 64 + ar)*K + (akq << 2);
    int bkk = tid >> 5, bcq = tid & 31;
    int bcol = bn + (bcq << 2);
    bool bok = bcol < Nn;
    const float* Bp0 = B + (size_t)bkk*Nn + bcol;
    const float* Bp1 = B + (size_t)(bkk + 8)*Nn + bcol;

    float acc[4][4][4];
    #pragma unroll
    for (int mt = 0; mt < 4; mt++)
        #pragma unroll
        for (int nt = 0; nt < 4; nt++)
            #pragma unroll
            for (int r = 0; r < 4; r++) acc[mt][nt][r] = 0.f;

    const float4 zero4 = make_float4(0.f, 0.f, 0.f, 0.f);

    {
        float4 a0 = *(const float4*)Ap0;
        float4 a1 = *(const float4*)Ap1;
        float4 b0 = bok ? *(const float4*)Bp0 : zero4;
        float4 b1 = bok ? *(const float4*)Bp1 : zero4;
        float av0[4] = {a0.x, a0.y, a0.z, a0.w};
        float av1[4] = {a1.x, a1.y, a1.z, a1.w};
        #pragma unroll
        for (int e = 0; e < 4; e++) {
            float h0 = __uint_as_float(f2tf32(av0[e]));
            float h1 = __uint_as_float(f2tf32(av1[e]));
            AH_(0, ar,      (akq<<2)+e) = h0;
            AL_(0, ar,      (akq<<2)+e) = __uint_as_float(f2tf32(av0[e] - h0));
            AH_(0, ar + 64, (akq<<2)+e) = h1;
            AL_(0, ar + 64, (akq<<2)+e) = __uint_as_float(f2tf32(av1[e] - h1));
        }
        float4 h, l;
        h.x = __uint_as_float(f2tf32(b0.x)); l.x = __uint_as_float(f2tf32(b0.x - h.x));
        h.y = __uint_as_float(f2tf32(b0.y)); l.y = __uint_as_float(f2tf32(b0.y - h.y));
        h.z = __uint_as_float(f2tf32(b0.z)); l.z = __uint_as_float(f2tf32(b0.z - h.z));
        h.w = __uint_as_float(f2tf32(b0.w)); l.w = __uint_as_float(f2tf32(b0.w - h.w));
        *(float4*)&BH_(0, bkk, bcq<<2) = h;
        *(float4*)&BL_(0, bkk, bcq<<2) = l;
        h.x = __uint_as_float(f2tf32(b1.x)); l.x = __uint_as_float(f2tf32(b1.x - h.x));
        h.y = __uint_as_float(f2tf32(b1.y)); l.y = __uint_as_float(f2tf32(b1.y - h.y));
        h.z = __uint_as_float(f2tf32(b1.z)); l.z = __uint_as_float(f2tf32(b1.z - h.z));
        h.w = __uint_as_float(f2tf32(b1.w)); l.w = __uint_as_float(f2tf32(b1.w - h.w));
        *(float4*)&BH_(0, bkk + 8, bcq<<2) = h;
        *(float4*)&BL_(0, bkk + 8, bcq<<2) = l;
        __syncthreads();
    }

    int T = K >> 4;
    for (int kt = 0; kt < T; kt++) {
        int cur = kt & 1, nxt = cur ^ 1;
        float4 a0, a1, b0, b1;
        if (kt < T - 1) {
            int k0 = (kt + 1) << 4;
            a0 = *(const float4*)(Ap0 + k0);
            a1 = *(const float4*)(Ap1 + k0);
            b0 = bok ? *(const float4*)(Bp0 + (size_t)k0*Nn) : zero4;
            b1 = bok ? *(const float4*)(Bp1 + (size_t)k0*Nn) : zero4;
        }
        #pragma unroll
        for (int k8 = 0; k8 < 16; k8 += 8) {
            unsigned bh[4][2], bl[4][2];
            #pragma unroll
            for (int nt = 0; nt < 4; nt++) {
                int c = wn + (nt << 3) + g;
                bh[nt][0] = __float_as_uint(BH_(cur, k8 + tg,     c));
                bh[nt][1] = __float_as_uint(BH_(cur, k8 + tg + 4, c));
                bl[nt][0] = __float_as_uint(BL_(cur, k8 + tg,     c));
                bl[nt][1] = __float_as_uint(BL_(cur, k8 + tg + 4, c));
            }
            #pragma unroll
            for (int mt = 0; mt < 4; mt++) {
                int r = wm + (mt << 4) + g;
                unsigned ah[4], al[4];
                ah[0] = __float_as_uint(AH_(cur, r,     k8 + tg));
                ah[1] = __float_as_uint(AH_(cur, r + 8, k8 + tg));
                ah[2] = __float_as_uint(AH_(cur, r,     k8 + tg + 4));
                ah[3] = __float_as_uint(AH_(cur, r + 8, k8 + tg + 4));
                al[0] = __float_as_uint(AL_(cur, r,     k8 + tg));
                al[1] = __float_as_uint(AL_(cur, r + 8, k8 + tg));
                al[2] = __float_as_uint(AL_(cur, r,     k8 + tg + 4));
                al[3] = __float_as_uint(AL_(cur, r + 8, k8 + tg + 4));
                #pragma unroll
                for (int nt = 0; nt < 4; nt++) {
                    mma_tf32(acc[mt][nt], ah, bh[nt]);
                    mma_tf32(acc[mt][nt], al, bh[nt]);
                    mma_tf32(acc[mt][nt], ah, bl[nt]);
                }
            }
        }
        if (kt < T - 1) {
            float av0[4] = {a0.x, a0.y, a0.z, a0.w};
            float av1[4] = {a1.x, a1.y, a1.z, a1.w};
            #pragma unroll
            for (int e = 0; e < 4; e++) {
                float h0 = __uint_as_float(f2tf32(av0[e]));
                float h1 = __uint_as_float(f2tf32(av1[e]));
                AH_(nxt, ar,      (akq<<2)+e) = h0;
                AL_(nxt, ar,      (akq<<2)+e) = __uint_as_float(f2tf32(av0[e] - h0));
                AH_(nxt, ar + 64, (akq<<2)+e) = h1;
                AL_(nxt, ar + 64, (akq<<2)+e) = __uint_as_float(f2tf32(av1[e] - h1));
            }
            float4 h, l;
            h.x = __uint_as_float(f2tf32(b0.x)); l.x = __uint_as_float(f2tf32(b0.x - h.x));
            h.y = __uint_as_float(f2tf32(b0.y)); l.y = __uint_as_float(f2tf32(b0.y - h.y));
            h.z = __uint_as_float(f2tf32(b0.z)); l.z = __uint_as_float(f2tf32(b0.z - h.z));
            h.w = __uint_as_float(f2tf32(b0.w)); l.w = __uint_as_float(f2tf32(b0.w - h.w));
            *(float4*)&BH_(nxt, bkk, bcq<<2) = h;
            *(float4*)&BL_(nxt, bkk, bcq<<2) = l;
            h.x = __uint_as_float(f2tf32(b1.x)); l.x = __uint_as_float(f2tf32(b1.x - h.x));
            h.y = __uint_as_float(f2tf32(b1.y)); l.y = __uint_as_float(f2tf32(b1.y - h.y));
            h.z = __uint_as_float(f2tf32(b1.z)); l.z = __uint_as_float(f2tf32(b1.z - h.z));
            h.w = __uint_as_float(f2tf32(b1.w)); l.w = __uint_as_float(f2tf32(b1.w - h.w));
            *(float4*)&BH_(nxt, bkk + 8, bcq<<2) = h;
            *(float4*)&BL_(nxt, bkk + 8, bcq<<2) = l;
            __syncthreads();
        }
    }

    #pragma unroll
    for (int mt = 0; mt < 4; mt++) {
        #pragma unroll
        for (int nt = 0; nt < 4; nt++) {
            int r0 = bm + wm + (mt << 4) + g;
            int cc = bn + wn + (nt << 3) + (tg << 1);
            float* p0 = C + (size_t)r0 * Nn + cc;
            float* p1 = C + (size_t)(r0 + 8) * Nn + cc;
            float v00 = acc[mt][nt][0], v01 = acc[mt][nt][1];
            float v10 = acc[mt][nt][2], v11 = acc[mt][nt][3];
            if (EPI == 0) {
                if (QKV && gate) {
                    if (cc < 24) {
                        *(float2*)p0 = make_float2(1.f/(1.f+expf(-v00)), 1.f/(1.f+expf(-v01)));
                        *(float2*)p1 = make_float2(1.f/(1.f+expf(-v10)), 1.f/(1.f+expf(-v11)));
                    }
                } else {
                    *(float2*)p0 = make_float2(v00, v01);
                    *(float2*)p1 = make_float2(v10, v11);
                }
            } else if (EPI == 2) {
                float b0v = bias[cc], b1v = bias[cc + 1];
                float z;
                z = v00 + b0v; v00 = z > 0.f ? z : 0.01f*z;
                z = v01 + b1v; v01 = z > 0.f ? z : 0.01f*z;
                z = v10 + b0v; v10 = z > 0.f ? z : 0.01f*z;
                z = v11 + b1v; v11 = z > 0.f ? z : 0.01f*z;
                *(float2*)p0 = make_float2(v00, v01);
                *(float2*)p1 = make_float2(v10, v11);
            } else if (EPI == 3) {
                float b0v = bias[cc], b1v = bias[cc + 1];
                float2 o0 = *(float2*)p0, o1 = *(float2*)p1;
                o0.x += v00 + b0v; o0.y += v01 + b1v;
                o1.x += v10 + b0v; o1.y += v11 + b1v;
                *(float2*)p0 = o0;
                *(float2*)p1 = o1;
            } else if (EPI == 4) {
                float2 o0 = *(float2*)p0, o1 = *(float2*)p1;
                o0.x += v00; o0.y += v01;
                o1.x += v10; o1.y += v11;
                *(float2*)p0 = o0;
                *(float2*)p1 = o1;
            }
        }
    }
}

// ---------------- KV mean-pool: K -> tf32 hi/lo pair, V -> fp32, [B,H,NB,DH] --
__global__ void pool_kernel(const float* __restrict__ k, const float* __restrict__ v,
                            float* __restrict__ kch, float* __restrict__ kcl,
                            float* __restrict__ vc)
{
    int wid = (blockIdx.x * blockDim.x + threadIdx.x) >> 5;
    int lane = threadIdx.x & 31;
    if (wid >= BB*HH*NB) return;
    int n = wid % NB;
    int h = (wid / NB) % HH;
    int b = wid / (NB*HH);
    float sk = 0.f, sv = 0.f;
    #pragma unroll
    for (int c = 0; c < 4; c++) {
        size_t idx = ((size_t)(b*SS + n*4 + c)*HH + h)*DHH + lane;
        sk += k[idx]; sv += v[idx];
    }
    size_t oidx = (((size_t)(b*HH + h))*NB + n)*DHH + lane;
    float m = sk * 0.25f;
    float fh = __uint_as_float(f2tf32(m));
    kch[oidx] = fh;
    kcl[oidx] = __uint_as_float(f2tf32(m - fh));
    vc[oidx]  = sv * 0.25f;
}

// ---------------- fused NSA attention (hybrid: MMA scores + scalar softmax) ---
// 128-thread blocks, 64 queries. Scores S[64xTN] = Q.Kc^T computed with 3xTF32
// tensor-core MMA into smem; masking/top-1/online-softmax/V-accum stay scalar
// (2 threads per query, each owning half of dh). KV tiles double-buffered.
__global__ void __launch_bounds__(128, 6) nsa_attn_kernel(
    const float* __restrict__ q, const float* __restrict__ k, const float* __restrict__ v,
    const float* __restrict__ kch, const float* __restrict__ kcl, const float* __restrict__ vc,
    const float* __restrict__ g, float* __restrict__ o)
{
    __shared__ float khs[2][TN][36];
    __shared__ float kls[2][TN][36];
    __shared__ float vcs[2][TN][36];
    __shared__ float ss[64][20];

    int tid   = threadIdx.x;
    int qtile = (NQT3 - 1) - (blockIdx.x & (NQT3 - 1));  // heavy first
    int h     = (blockIdx.x >> 5) & (HH - 1);
    int b     = blockIdx.x >> 8;
    int qi    = tid >> 1;
    int half  = tid & 1;
    int t     = qtile * QT3 + qi;
    int lane  = tid & 31, wid = tid >> 5;
    int gq    = lane >> 2, tg = lane & 3;
    unsigned pmask = 3u << (tid & 30);

    const float SCALE2 = 0.17677669529663687f * 1.4426950408889634f;  // scale*log2e

    // ---- Q fragments (A operand, 3xTF32) for this warp's 16 query rows ----
    unsigned ah[4][4], al[4][4];
    {
        int r0 = qtile * QT3 + 16*wid + gq;
        const float* q0 = q + ((size_t)(b*SS + r0    )*HH + h)*DHH;
        const float* q1 = q + ((size_t)(b*SS + r0 + 8)*HH + h)*DHH;
        #pragma unroll
        for (int k8 = 0; k8 < 4; k8++) {
            float f0 = q0[k8*8 + tg    ] * SCALE2;
            float f1 = q1[k8*8 + tg    ] * SCALE2;
            float f2 = q0[k8*8 + tg + 4] * SCALE2;
            float f3 = q1[k8*8 + tg + 4] * SCALE2;
            ah[k8][0] = f2tf32(f0); al[k8][0] = f2tf32(f0 - __uint_as_float(ah[k8][0]));
            ah[k8][1] = f2tf32(f1); al[k8][1] = f2tf32(f1 - __uint_as_float(ah[k8][1]));
            ah[k8][2] = f2tf32(f2); al[k8][2] = f2tf32(f2 - __uint_as_float(ah[k8][2]));
            ah[k8][3] = f2tf32(f3); al[k8][3] = f2tf32(f3 - __uint_as_float(ah[k8][3]));
        }
    }

    int own = t >> 2;
    size_t bh_off = ((size_t)(b*HH + h))*NB*DHH;
    const float* kchb = kch + bh_off;
    const float* kclb = kcl + bh_off;
    const float* vcb  = vc  + bh_off;

    float Ml = -INFINITY, Z = 0.f;
    ull av2[8];
    #pragma unroll
    for (int j = 0; j < 8; j++) av2[j] = 0ull;
    float bval = -INFINITY; int bidx = NB;

    // tile loader: TN rows x 32 floats per array; 128 threads -> 1 float4 each
    int ldrow = tid >> 3, ldc4 = tid & 7;
    size_t ldsrc = (size_t)ldrow*DHH + (ldc4 << 2);

    // prologue: tile 0 -> buffer 0
    cp_async16(&khs[0][ldrow][ldc4 << 2], kchb + ldsrc);
    cp_async16(&kls[0][ldrow][ldc4 << 2], kclb + ldsrc);
    cp_async16(&vcs[0][ldrow][ldc4 << 2], vcb  + ldsrc);
    CP_COMMIT();
    CP_WAIT0();
    __syncthreads();

    for (int tile = 0; tile <= qtile; tile++) {
        int cur = tile & 1, nxt = cur ^ 1;
        int n0 = tile * TN;
        if (tile < qtile) {
            size_t nsrc = (size_t)(n0 + TN)*DHH + ldsrc;
            cp_async16(&khs[nxt][ldrow][ldc4 << 2], kchb + nsrc);
            cp_async16(&kls[nxt][ldrow][ldc4 << 2], kclb + nsrc);
            cp_async16(&vcs[nxt][ldrow][ldc4 << 2], vcb  + nsrc);
            CP_COMMIT();
        }

        // ---- score MMA: S[64xTN] = Q . Kc^T (3xTF32) -> ss ----
        #pragma unroll
        for (int nt = 0; nt < 2; nt++) {
            float cf[4] = {0.f, 0.f, 0.f, 0.f};
            #pragma unroll
            for (int k8 = 0; k8 < 4; k8++) {
                int row = nt*8 + gq;
                int c0 = k8*8 + tg, c1 = c0 + 4;
                unsigned bh[2], bl[2];
                bh[0] = __float_as_uint(khs[cur][row][c0]);
                bh[1] = __float_as_uint(khs[cur][row][c1]);
                bl[0] = __float_as_uint(kls[cur][row][c0]);
                bl[1] = __float_as_uint(kls[cur][row][c1]);
                mma_tf32(cf, ah[k8], bh);
                mma_tf32(cf, al[k8], bh);
                mma_tf32(cf, ah[k8], bl);
            }
            int sr = 16*wid + gq, sc = nt*8 + (tg << 1);
            *(float2*)&ss[sr    ][sc] = make_float2(cf[0], cf[1]);
            *(float2*)&ss[sr + 8][sc] = make_float2(cf[2], cf[3]);
        }
        __syncthreads();

        // ---- scalar phase: mask, top-1, online softmax, V accumulation ----
        int lim = (tile == qtile) ? ((qi + 1) >> 2) : TN;

        for (int n4 = 0; n4 < TN; n4 += 4) {
            if (n4 >= lim) break;
            float4 s4 = *(const float4*)&ss[qi][n4];
            float s0 = s4.x, s1 = s4.y, s2 = s4.z, s3 = s4.w;

            if (n4 + 1 >= lim) s1 = -INFINITY;
            if (n4 + 2 >= lim) s2 = -INFINITY;
            if (n4 + 3 >= lim) s3 = -INFINITY;

            int gn = n0 + n4;
            if (gn + 0 != own && s0 > bval) { bval = s0; bidx = gn + 0; }
            if (gn + 1 != own && s1 > bval) { bval = s1; bidx = gn + 1; }
            if (gn + 2 != own && s2 > bval) { bval = s2; bidx = gn + 2; }
            if (gn + 3 != own && s3 > bval) { bval = s3; bidx = gn + 3; }

            float m4 = fmaxf(fmaxf(s0, s1), fmaxf(s2, s3));
            float Mn = fmaxf(Ml, m4);
            float r  = ex2(Ml - Mn);
            ull rr = pk2(r, r);
            Z *= r;
            #pragma unroll
            for (int j = 0; j < 8; j++) av2[j] = mul2(av2[j], rr);
            Ml = Mn;

            float p0 = ex2(s0 - Ml);
            float p1 = ex2(s1 - Ml);
            float p2 = ex2(s2 - Ml);
            float p3 = ex2(s3 - Ml);
            Z += (p0 + p1) + (p2 + p3);
            ull pp0 = pk2(p0, p0), pp1 = pk2(p1, p1);
            ull pp2 = pk2(p2, p2), pp3 = pk2(p3, p3);
            const ulonglong2* v0 = (const ulonglong2*)&vcs[cur][n4+0][half << 4];
            const ulonglong2* v1 = (const ulonglong2*)&vcs[cur][n4+1][half << 4];
            const ulonglong2* v2 = (const ulonglong2*)&vcs[cur][n4+2][half << 4];
            const ulonglong2* v3 = (const ulonglong2*)&vcs[cur][n4+3][half << 4];
            #pragma unroll
            for (int j = 0; j < 4; j++) {
                ulonglong2 w0 = v0[j], w1 = v1[j], w2 = v2[j], w3 = v3[j];
                av2[2*j]   = fma2(pp0, w0.x, av2[2*j]);
                av2[2*j+1] = fma2(pp0, w0.y, av2[2*j+1]);
                av2[2*j]   = fma2(pp1, w1.x, av2[2*j]);
                av2[2*j+1] = fma2(pp1, w1.y, av2[2*j+1]);
                av2[2*j]   = fma2(pp2, w2.x, av2[2*j]);
                av2[2*j+1] = fma2(pp2, w2.y, av2[2*j+1]);
                av2[2*j]   = fma2(pp3, w3.x, av2[2*j]);
                av2[2*j+1] = fma2(pp3, w3.y, av2[2*j+1]);
            }
        }

        // end-of-tile barrier: everyone done with ss & cur buffers; next data ready
        if (tile < qtile) CP_WAIT0();
        __syncthreads();
    }

    if (bval == -INFINITY) bidx = (own == 0) ? 1 : 0;

    // rebuild packed q (half-dh) for selection + window branches
    size_t qoff = ((size_t)(b*SS + t)*HH + h)*DHH + (half << 4);
    ull qp[8];
    {
        const float4* qr = (const float4*)(q + qoff);
        #pragma unroll
        for (int i = 0; i < 4; i++) {
            float4 f = qr[i];
            qp[2*i]   = pk2(f.x * SCALE2, f.y * SCALE2);
            qp[2*i+1] = pk2(f.z * SCALE2, f.w * SCALE2);
        }
    }

    const float* gr = g + (size_t)(b*SS + t)*24;
    float g0 = gr[h], g1 = gr[8 + h], g2 = gr[16 + h];

    float invZ = (Z > 0.f) ? (1.f / Z) : 0.f;
    {
        ull c0p = pk2(g0 * invZ, g0 * invZ);
        #pragma unroll
        for (int j = 0; j < 8; j++) av2[j] = mul2(av2[j], c0p);
    }

    // ---- selection branch: blocks {own, bidx}, 8 keys, mask pos<=t ----
    float sc[8];
    float smax = -INFINITY;
    #pragma unroll
    for (int e = 0; e < 8; e++) {
        int pos = ((e < 4) ? own : bidx) * 4 + (e & 3);
        const ulonglong2* kr = (const ulonglong2*)(k + ((size_t)(b*SS + pos)*HH + h)*DHH + (half << 4));
        ull acc = 0;
        #pragma unroll
        for (int i = 0; i < 4; i++) {
            ulonglong2 kk2 = kr[i];
            acc = fma2(qp[2*i], kk2.x, acc);
            acc = fma2(qp[2*i+1], kk2.y, acc);
        }
        float lo, hi; upk2(lo, hi, acc);
        float sv = lo + hi;
        sv += __shfl_xor_sync(pmask, sv, 1);
        sv = (pos <= t) ? sv : -INFINITY;
        sc[e] = sv;
        smax = fmaxf(smax, sv);
    }
    float zf = 0.f;
    #pragma unroll
    for (int e = 0; e < 8; e++) { sc[e] = ex2(sc[e] - smax); zf += sc[e]; }
    float c1 = g1 / zf;
    #pragma unroll
    for (int e = 0; e < 8; e++) {
        int pos = ((e < 4) ? own : bidx) * 4 + (e & 3);
        ull ww = pk2(sc[e] * c1, sc[e] * c1);
        const ulonglong2* vr = (const ulonglong2*)(v + ((size_t)(b*SS + pos)*HH + h)*DHH + (half << 4));
        #pragma unroll
        for (int i = 0; i < 4; i++) {
            ulonglong2 vv = vr[i];
            av2[2*i]   = fma2(ww, vv.x, av2[2*i]);
            av2[2*i+1] = fma2(ww, vv.y, av2[2*i+1]);
        }
    }

    // ---- sliding-window branch: keys {t-1, t} ----
    int tp = (t > 0) ? t - 1 : 0;
    float s1w, s0w;
    {
        const ulonglong2* kr1 = (const ulonglong2*)(k + ((size_t)(b*SS + t )*HH + h)*DHH + (half << 4));
        const ulonglong2* kr0 = (const ulonglong2*)(k + ((size_t)(b*SS + tp)*HH + h)*DHH + (half << 4));
        ull ac1 = 0, ac0 = 0;
        #pragma unroll
        for (int i = 0; i < 4; i++) {
            ulonglong2 k1 = kr1[i], k0 = kr0[i];
            ac1 = fma2(qp[2*i], k1.x, ac1); ac1 = fma2(qp[2*i+1], k1.y, ac1);
            ac0 = fma2(qp[2*i], k0.x, ac0); ac0 = fma2(qp[2*i+1], k0.y, ac0);
        }
        float lo, hi;
        upk2(lo, hi, ac1); s1w = lo + hi;
        upk2(lo, hi, ac0); s0w = lo + hi;
        s1w += __shfl_xor_sync(pmask, s1w, 1);
        s0w += __shfl_xor_sync(pmask, s0w, 1);
    }
    if (t == 0) s0w = -INFINITY;
    float wm = fmaxf(s0w, s1w);
    float p0w = ex2(s0w - wm), p1w = ex2(s1w - wm);
    float c2 = g2 / (p0w + p1w);
    {
        ull w0p = pk2(p0w * c2, p0w * c2);
        ull w1p = pk2(p1w * c2, p1w * c2);
        const ulonglong2* vr1 = (const ulonglong2*)(v + ((size_t)(b*SS + t )*HH + h)*DHH + (half << 4));
        const ulonglong2* vr0 = (const ulonglong2*)(v + ((size_t)(b*SS + tp)*HH + h)*DHH + (half << 4));
        #pragma unroll
        for (int i = 0; i < 4; i++) {
            ulonglong2 v1 = vr1[i], v0 = vr0[i];
            av2[2*i]   = fma2(w1p, v1.x, fma2(w0p, v0.x, av2[2*i]));
            av2[2*i+1] = fma2(w1p, v1.y, fma2(w0p, v0.y, av2[2*i+1]));
        }
    }

    ulonglong2* orow = (ulonglong2*)(o + qoff);
    #pragma unroll
    for (int j = 0; j < 4; j++) {
        ulonglong2 w2;
        w2.x = av2[2*j]; w2.y = av2[2*j+1];
        orow[j] = w2;
    }
}

// ---------------- host orchestration ----------------
extern "C" void kernel_launch(void* const* d_in, const int* in_sizes, int n_in,
                              void* d_out, int out_size)
{
    const float* x_in   = (const float*)d_in[0];
    const float* ln_a_g = (const float*)d_in[1];
    const float* ln_a_b = (const float*)d_in[2];
    const float* Wq     = (const float*)d_in[3];
    const float* Wk     = (const float*)d_in[4];
    const float* Wv     = (const float*)d_in[5];
    const float* Wg     = (const float*)d_in[6];
    const float* Wo     = (const float*)d_in[7];
    const float* ln_f_g = (const float*)d_in[8];
    const float* ln_f_b = (const float*)d_in[9];
    const float* W1     = (const float*)d_in[10];
    const float* b1     = (const float*)d_in[11];
    const float* W2     = (const float*)d_in[12];
    const float* b2     = (const float*)d_in[13];
    float* x = (float*)d_out;

    float *ph, *pq, *pk, *pv, *po, *pg, *pkch, *pkcl, *pvc, *pmid;
    cudaGetSymbolAddress((void**)&ph,   g_h);
    cudaGetSymbolAddress((void**)&pq,   g_q);
    cudaGetSymbolAddress((void**)&pk,   g_k);
    cudaGetSymbolAddress((void**)&pv,   g_v);
    cudaGetSymbolAddress((void**)&po,   g_o);
    cudaGetSymbolAddress((void**)&pg,   g_g);
    cudaGetSymbolAddress((void**)&pkch, g_kch);
    cudaGetSymbolAddress((void**)&pkcl, g_kcl);
    cudaGetSymbolAddress((void**)&pvc,  g_vc);
    cudaGetSymbolAddress((void**)&pmid, g_mid);

    cudaFuncSetAttribute(mma_gemm_kernel<0, true>,  cudaFuncAttributeMaxDynamicSharedMemorySize, GEMM_SMEM_BYTES);
    cudaFuncSetAttribute(mma_gemm_kernel<4, false>, cudaFuncAttributeMaxDynamicSharedMemorySize, GEMM_SMEM_BYTES);
    cudaFuncSetAttribute(mma_gemm_kernel<2, false>, cudaFuncAttributeMaxDynamicSharedMemorySize, GEMM_SMEM_BYTES);
    cudaFuncSetAttribute(mma_gemm_kernel<3, false>, cudaFuncAttributeMaxDynamicSharedMemorySize, GEMM_SMEM_BYTES);

    cudaMemcpyAsync(x, x_in, (size_t)BSD * sizeof(float), cudaMemcpyDeviceToDevice, 0);

    for (int l = 0; l < 2; l++) {
        for (int j2 = 0; j2 < 2; j2++) {
            int li = l*2 + j2;
            ln_kernel<<<BS/8, 256>>>(x, ln_a_g + li*DIMM, ln_a_b + li*DIMM, ph);
            mma_gemm_kernel<0, true><<<dim3(2, 64, 4), 256, GEMM_SMEM_BYTES>>>(
                ph,
                Wq + (size_t)li*DIMM*DIMM, Wk + (size_t)li*DIMM*DIMM,
                Wv + (size_t)li*DIMM*DIMM, Wg + (size_t)li*DIMM*24,
                nullptr, pq, pk, pv, pg, BS, DIMM, DIMM);
            pool_kernel<<<(BB*HH*NB*32)/256, 256>>>(pk, pv, pkch, pkcl, pvc);
            nsa_attn_kernel<<<BB*HH*NQT3, 128>>>(pq, pk, pv, pkch, pkcl, pvc, pg, po);
            mma_gemm_kernel<4, false><<<dim3(2, 64), 256, GEMM_SMEM_BYTES>>>(
                po, Wo + (size_t)li*DIMM*DIMM, nullptr, nullptr, nullptr,
                nullptr, x, nullptr, nullptr, nullptr, BS, DIMM, DIMM);
        }
        ln_kernel<<<BS/8, 256>>>(x, ln_f_g + l*DIMM, ln_f_b + l*DIMM, ph);
        mma_gemm_kernel<2, false><<<dim3(4, 64), 256, GEMM_SMEM_BYTES>>>(
            ph, W1 + (size_t)l*DIMM*512, nullptr, nullptr, nullptr,
            b1 + l*512, pmid, nullptr, nullptr, nullptr, BS, 512, DIMM);
        mma_gemm_kernel<3, false><<<dim3(2, 64), 256, GEMM_SMEM_BYTES>>>(
            pmid, W2 + (size_t)l*512*DIMM, nullptr, nullptr, nullptr,
            b2 + l*DIMM, x, nullptr, nullptr, nullptr, BS, DIMM, 512);
    }
}

// round 17
// speedup vs baseline: 1.0874x; 1.0874x over previous
#include <cuda_runtime.h>
#include <math.h>

#define BB   4
#define SS   2048
#define HH   8
#define DHH  32
#define DIMM 256
#define NB   512          // SS / 4 compressed blocks
#define BS   (BB*SS)      // 8192 rows
#define BSD  (BS*DIMM)    // 2097152 floats
#define QT3  64           // queries per attn block
#define NQT3 (SS/QT3)     // 32 qtiles
#define TN   16           // kv-tile width (pooled blocks)

typedef unsigned long long ull;

// ---------------- scratch (static device buffers; no allocs) ----------------
__device__ float g_h  [BSD];
__device__ float g_q  [BSD];
__device__ float g_k  [BSD];
__device__ float g_v  [BSD];
__device__ float g_o  [BSD];
__device__ float g_g  [BS*24];
__device__ float g_kch[BB*HH*NB*DHH];   // pooled K, tf32 hi
__device__ float g_kcl[BB*HH*NB*DHH];   // pooled K, tf32 lo (residual)
__device__ float g_vc [BB*HH*NB*DHH];   // pooled V, fp32
__device__ float g_mid[BS*512];

__device__ __forceinline__ void cp_async16(void* smem, const void* gmem) {
    unsigned saddr = (unsigned)__cvta_generic_to_shared(smem);
    asm volatile("cp.async.ca.shared.global [%0], [%1], 16;\n" :: "r"(saddr), "l"(gmem));
}
#define CP_COMMIT() asm volatile("cp.async.commit_group;\n" ::: "memory")
#define CP_WAIT0()  asm volatile("cp.async.wait_group 0;\n" ::: "memory")

__device__ __forceinline__ unsigned f2tf32(float x) {
    unsigned u; asm("cvt.rna.tf32.f32 %0, %1;" : "=r"(u) : "f"(x)); return u;
}

__device__ __forceinline__ void mma_tf32(float* c, const unsigned* a, const unsigned* b) {
    asm volatile(
        "mma.sync.aligned.m16n8k8.row.col.f32.tf32.tf32.f32 "
        "{%0,%1,%2,%3}, {%4,%5,%6,%7}, {%8,%9}, {%0,%1,%2,%3};"
        : "+f"(c[0]), "+f"(c[1]), "+f"(c[2]), "+f"(c[3])
        : "r"(a[0]), "r"(a[1]), "r"(a[2]), "r"(a[3]), "r"(b[0]), "r"(b[1]));
}

// ---------------- packed f32x2 helpers ----------------
__device__ __forceinline__ ull pk2(float lo, float hi) {
    ull r; asm("mov.b64 %0, {%1,%2};" : "=l"(r) : "f"(lo), "f"(hi)); return r;
}
__device__ __forceinline__ void upk2(float& lo, float& hi, ull v) {
    asm("mov.b64 {%0,%1}, %2;" : "=f"(lo), "=f"(hi) : "l"(v));
}
__device__ __forceinline__ ull fma2(ull a, ull b, ull c) {
    ull d; asm("fma.rn.f32x2 %0, %1, %2, %3;" : "=l"(d) : "l"(a), "l"(b), "l"(c)); return d;
}
__device__ __forceinline__ ull mul2(ull a, ull b) {
    ull d; asm("mul.rn.f32x2 %0, %1, %2;" : "=l"(d) : "l"(a), "l"(b)); return d;
}
__device__ __forceinline__ float ex2(float x) {
    float y; asm("ex2.approx.f32 %0, %1;" : "=f"(y) : "f"(x)); return y;
}

// ---------------- LayerNorm: one warp per row of 256 ----------------
__global__ void ln_kernel(const float* __restrict__ x, const float* __restrict__ gw,
                          const float* __restrict__ bw, float* __restrict__ out)
{
    int warp = (blockIdx.x * blockDim.x + threadIdx.x) >> 5;
    int lane = threadIdx.x & 31;
    if (warp >= BS) return;
    const float* xr = x + (size_t)warp * DIMM;
    float vbuf[8];
    float s = 0.f;
    #pragma unroll
    for (int i = 0; i < 8; i++) { vbuf[i] = xr[lane + i*32]; s += vbuf[i]; }
    #pragma unroll
    for (int o = 16; o > 0; o >>= 1) s += __shfl_xor_sync(~0u, s, o);
    float m = s * (1.f/256.f);
    float sq = 0.f;
    #pragma unroll
    for (int i = 0; i < 8; i++) { float d = vbuf[i] - m; sq += d*d; }
    #pragma unroll
    for (int o = 16; o > 0; o >>= 1) sq += __shfl_xor_sync(~0u, sq, o);
    float rstd = rsqrtf(sq * (1.f/256.f) + 1e-5f);
    float* orow = out + (size_t)warp * DIMM;
    #pragma unroll
    for (int i = 0; i < 8; i++) {
        int c = lane + i*32;
        orow[c] = (vbuf[i] - m) * rstd * gw[c] + bw[c];
    }
}

// ---------------- main GEMM: 3xTF32 tensor-core, 128x128 tile, BK=16 --------
#define AH_(b,r,c) sAh[((b)*128 + (r))*20 + (c)]
#define AL_(b,r,c) sAl[((b)*128 + (r))*20 + (c)]
#define BH_(b,k,c) sBh[((b)*16  + (k))*136 + (c)]
#define BL_(b,k,c) sBl[((b)*16  + (k))*136 + (c)]
#define GEMM_SMEM_BYTES ((2*128*20*2 + 2*16*136*2) * 4)

template<int EPI, bool QKV>
__global__ void __launch_bounds__(256, 2) mma_gemm_kernel(
    const float* __restrict__ A,
    const float* __restrict__ B0, const float* __restrict__ B1,
    const float* __restrict__ B2, const float* __restrict__ B3,
    const float* __restrict__ bias,
    float* __restrict__ C0, float* __restrict__ C1,
    float* __restrict__ C2, float* __restrict__ C3,
    int M, int N, int K)
{
    extern __shared__ float sm_[];
    float* sAh = sm_;
    float* sAl = sAh + 2*128*20;
    float* sBh = sAl + 2*128*20;
    float* sBl = sBh + 2*16*136;

    const float* B = B0;
    float* C = C0;
    int Nn = N;
    bool gate = false;
    if (QKV) {
        if (blockIdx.z == 1)      { B = B1; C = C1; }
        else if (blockIdx.z == 2) { B = B2; C = C2; }
        else if (blockIdx.z == 3) {
            if (blockIdx.x > 0) return;
            B = B3; C = C3; Nn = 24; gate = true;
        }
    }

    int tid  = threadIdx.x;
    int wid  = tid >> 5, lane = tid & 31;
    int g    = lane >> 2, tg = lane & 3;
    int wm   = (wid >> 2) << 6;
    int wn   = (wid & 3) << 5;
    int bm   = blockIdx.y << 7, bn = blockIdx.x << 7;

    int ar  = tid >> 2, akq = tid & 3;
    const float* Ap0 = A + (size_t)(bm + ar)*K + (akq << 2);
    const float* Ap1 = A + (size_t)(bm + 64 + ar)*K + (akq << 2);
    int bkk = tid >> 5, bcq = tid & 31;
    int bcol = bn + (bcq << 2);
    bool bok = bcol < Nn;
    const float* Bp0 = B + (size_t)bkk*Nn + bcol;
    const float* Bp1 = B + (size_t)(bkk + 8)*Nn + bcol;

    float acc[4][4][4];
    #pragma unroll
    for (int mt = 0; mt < 4; mt++)
        #pragma unroll
        for (int nt = 0; nt < 4; nt++)
            #pragma unroll
            for (int r = 0; r < 4; r++) acc[mt][nt][r] = 0.f;

    const float4 zero4 = make_float4(0.f, 0.f, 0.f, 0.f);

    {
        float4 a0 = *(const float4*)Ap0;
        float4 a1 = *(const float4*)Ap1;
        float4 b0 = bok ? *(const float4*)Bp0 : zero4;
        float4 b1 = bok ? *(const float4*)Bp1 : zero4;
        float av0[4] = {a0.x, a0.y, a0.z, a0.w};
        float av1[4] = {a1.x, a1.y, a1.z, a1.w};
        #pragma unroll
        for (int e = 0; e < 4; e++) {
            float h0 = __uint_as_float(f2tf32(av0[e]));
            float h1 = __uint_as_float(f2tf32(av1[e]));
            AH_(0, ar,      (akq<<2)+e) = h0;
            AL_(0, ar,      (akq<<2)+e) = __uint_as_float(f2tf32(av0[e] - h0));
            AH_(0, ar + 64, (akq<<2)+e) = h1;
            AL_(0, ar + 64, (akq<<2)+e) = __uint_as_float(f2tf32(av1[e] - h1));
        }
        float4 h, l;
        h.x = __uint_as_float(f2tf32(b0.x)); l.x = __uint_as_float(f2tf32(b0.x - h.x));
        h.y = __uint_as_float(f2tf32(b0.y)); l.y = __uint_as_float(f2tf32(b0.y - h.y));
        h.z = __uint_as_float(f2tf32(b0.z)); l.z = __uint_as_float(f2tf32(b0.z - h.z));
        h.w = __uint_as_float(f2tf32(b0.w)); l.w = __uint_as_float(f2tf32(b0.w - h.w));
        *(float4*)&BH_(0, bkk, bcq<<2) = h;
        *(float4*)&BL_(0, bkk, bcq<<2) = l;
        h.x = __uint_as_float(f2tf32(b1.x)); l.x = __uint_as_float(f2tf32(b1.x - h.x));
        h.y = __uint_as_float(f2tf32(b1.y)); l.y = __uint_as_float(f2tf32(b1.y - h.y));
        h.z = __uint_as_float(f2tf32(b1.z)); l.z = __uint_as_float(f2tf32(b1.z - h.z));
        h.w = __uint_as_float(f2tf32(b1.w)); l.w = __uint_as_float(f2tf32(b1.w - h.w));
        *(float4*)&BH_(0, bkk + 8, bcq<<2) = h;
        *(float4*)&BL_(0, bkk + 8, bcq<<2) = l;
        __syncthreads();
    }

    int T = K >> 4;
    for (int kt = 0; kt < T; kt++) {
        int cur = kt & 1, nxt = cur ^ 1;
        float4 a0, a1, b0, b1;
        if (kt < T - 1) {
            int k0 = (kt + 1) << 4;
            a0 = *(const float4*)(Ap0 + k0);
            a1 = *(const float4*)(Ap1 + k0);
            b0 = bok ? *(const float4*)(Bp0 + (size_t)k0*Nn) : zero4;
            b1 = bok ? *(const float4*)(Bp1 + (size_t)k0*Nn) : zero4;
        }
        #pragma unroll
        for (int k8 = 0; k8 < 16; k8 += 8) {
            unsigned bh[4][2], bl[4][2];
            #pragma unroll
            for (int nt = 0; nt < 4; nt++) {
                int c = wn + (nt << 3) + g;
                bh[nt][0] = __float_as_uint(BH_(cur, k8 + tg,     c));
                bh[nt][1] = __float_as_uint(BH_(cur, k8 + tg + 4, c));
                bl[nt][0] = __float_as_uint(BL_(cur, k8 + tg,     c));
                bl[nt][1] = __float_as_uint(BL_(cur, k8 + tg + 4, c));
            }
            #pragma unroll
            for (int mt = 0; mt < 4; mt++) {
                int r = wm + (mt << 4) + g;
                unsigned ah[4], al[4];
                ah[0] = __float_as_uint(AH_(cur, r,     k8 + tg));
                ah[1] = __float_as_uint(AH_(cur, r + 8, k8 + tg));
                ah[2] = __float_as_uint(AH_(cur, r,     k8 + tg + 4));
                ah[3] = __float_as_uint(AH_(cur, r + 8, k8 + tg + 4));
                al[0] = __float_as_uint(AL_(cur, r,     k8 + tg));
                al[1] = __float_as_uint(AL_(cur, r + 8, k8 + tg));
                al[2] = __float_as_uint(AL_(cur, r,     k8 + tg + 4));
                al[3] = __float_as_uint(AL_(cur, r + 8, k8 + tg + 4));
                #pragma unroll
                for (int nt = 0; nt < 4; nt++) {
                    mma_tf32(acc[mt][nt], ah, bh[nt]);
                    mma_tf32(acc[mt][nt], al, bh[nt]);
                    mma_tf32(acc[mt][nt], ah, bl[nt]);
                }
            }
        }
        if (kt < T - 1) {
            float av0[4] = {a0.x, a0.y, a0.z, a0.w};
            float av1[4] = {a1.x, a1.y, a1.z, a1.w};
            #pragma unroll
            for (int e = 0; e < 4; e++) {
                float h0 = __uint_as_float(f2tf32(av0[e]));
                float h1 = __uint_as_float(f2tf32(av1[e]));
                AH_(nxt, ar,      (akq<<2)+e) = h0;
                AL_(nxt, ar,      (akq<<2)+e) = __uint_as_float(f2tf32(av0[e] - h0));
                AH_(nxt, ar + 64, (akq<<2)+e) = h1;
                AL_(nxt, ar + 64, (akq<<2)+e) = __uint_as_float(f2tf32(av1[e] - h1));
            }
            float4 h, l;
            h.x = __uint_as_float(f2tf32(b0.x)); l.x = __uint_as_float(f2tf32(b0.x - h.x));
            h.y = __uint_as_float(f2tf32(b0.y)); l.y = __uint_as_float(f2tf32(b0.y - h.y));
            h.z = __uint_as_float(f2tf32(b0.z)); l.z = __uint_as_float(f2tf32(b0.z - h.z));
            h.w = __uint_as_float(f2tf32(b0.w)); l.w = __uint_as_float(f2tf32(b0.w - h.w));
            *(float4*)&BH_(nxt, bkk, bcq<<2) = h;
            *(float4*)&BL_(nxt, bkk, bcq<<2) = l;
            h.x = __uint_as_float(f2tf32(b1.x)); l.x = __uint_as_float(f2tf32(b1.x - h.x));
            h.y = __uint_as_float(f2tf32(b1.y)); l.y = __uint_as_float(f2tf32(b1.y - h.y));
            h.z = __uint_as_float(f2tf32(b1.z)); l.z = __uint_as_float(f2tf32(b1.z - h.z));
            h.w = __uint_as_float(f2tf32(b1.w)); l.w = __uint_as_float(f2tf32(b1.w - h.w));
            *(float4*)&BH_(nxt, bkk + 8, bcq<<2) = h;
            *(float4*)&BL_(nxt, bkk + 8, bcq<<2) = l;
            __syncthreads();
        }
    }

    #pragma unroll
    for (int mt = 0; mt < 4; mt++) {
        #pragma unroll
        for (int nt = 0; nt < 4; nt++) {
            int r0 = bm + wm + (mt << 4) + g;
            int cc = bn + wn + (nt << 3) + (tg << 1);
            float* p0 = C + (size_t)r0 * Nn + cc;
            float* p1 = C + (size_t)(r0 + 8) * Nn + cc;
            float v00 = acc[mt][nt][0], v01 = acc[mt][nt][1];
            float v10 = acc[mt][nt][2], v11 = acc[mt][nt][3];
            if (EPI == 0) {
                if (QKV && gate) {
                    if (cc < 24) {
                        *(float2*)p0 = make_float2(1.f/(1.f+expf(-v00)), 1.f/(1.f+expf(-v01)));
                        *(float2*)p1 = make_float2(1.f/(1.f+expf(-v10)), 1.f/(1.f+expf(-v11)));
                    }
                } else {
                    *(float2*)p0 = make_float2(v00, v01);
                    *(float2*)p1 = make_float2(v10, v11);
                }
            } else if (EPI == 2) {
                float b0v = bias[cc], b1v = bias[cc + 1];
                float z;
                z = v00 + b0v; v00 = z > 0.f ? z : 0.01f*z;
                z = v01 + b1v; v01 = z > 0.f ? z : 0.01f*z;
                z = v10 + b0v; v10 = z > 0.f ? z : 0.01f*z;
                z = v11 + b1v; v11 = z > 0.f ? z : 0.01f*z;
                *(float2*)p0 = make_float2(v00, v01);
                *(float2*)p1 = make_float2(v10, v11);
            } else if (EPI == 3) {
                float b0v = bias[cc], b1v = bias[cc + 1];
                float2 o0 = *(float2*)p0, o1 = *(float2*)p1;
                o0.x += v00 + b0v; o0.y += v01 + b1v;
                o1.x += v10 + b0v; o1.y += v11 + b1v;
                *(float2*)p0 = o0;
                *(float2*)p1 = o1;
            } else if (EPI == 4) {
                float2 o0 = *(float2*)p0, o1 = *(float2*)p1;
                o0.x += v00; o0.y += v01;
                o1.x += v10; o1.y += v11;
                *(float2*)p0 = o0;
                *(float2*)p1 = o1;
            }
        }
    }
}

// ---------------- KV mean-pool: K -> tf32 hi/lo pair, V -> fp32, [B,H,NB,DH] --
__global__ void pool_kernel(const float* __restrict__ k, const float* __restrict__ v,
                            float* __restrict__ kch, float* __restrict__ kcl,
                            float* __restrict__ vc)
{
    int wid = (blockIdx.x * blockDim.x + threadIdx.x) >> 5;
    int lane = threadIdx.x & 31;
    if (wid >= BB*HH*NB) return;
    int n = wid % NB;
    int h = (wid / NB) % HH;
    int b = wid / (NB*HH);
    float sk = 0.f, sv = 0.f;
    #pragma unroll
    for (int c = 0; c < 4; c++) {
        size_t idx = ((size_t)(b*SS + n*4 + c)*HH + h)*DHH + lane;
        sk += k[idx]; sv += v[idx];
    }
    size_t oidx = (((size_t)(b*HH + h))*NB + n)*DHH + lane;
    float m = sk * 0.25f;
    float fh = __uint_as_float(f2tf32(m));
    kch[oidx] = fh;
    kcl[oidx] = __uint_as_float(f2tf32(m - fh));
    vc[oidx]  = sv * 0.25f;
}

// ---------------- fused NSA attention: full tensor-core flash -----------------
// 128-thread blocks, 64 queries. Score GEMM (3xTF32) AND P.V GEMM (tf32) on
// tensor cores; softmax bookkeeping scalar (2 threads/query). Warp-private
// rows => intra-tile syncs are __syncwarp; one block barrier per tile.
__global__ void __launch_bounds__(128, 5) nsa_attn_kernel(
    const float* __restrict__ q, const float* __restrict__ k, const float* __restrict__ v,
    const float* __restrict__ kch, const float* __restrict__ kcl, const float* __restrict__ vc,
    const float* __restrict__ g, float* __restrict__ o)
{
    __shared__ float khs[2][TN][36];
    __shared__ float kls[2][TN][36];
    __shared__ float vcs[2][TN][36];
    __shared__ float ss[64][20];    // scores, then P (overwritten in place)
    __shared__ float rr_s[64];      // per-query rescale factor
    __shared__ float ocs[64][36];   // compressed-branch output staging

    int tid   = threadIdx.x;
    int qtile = (NQT3 - 1) - (blockIdx.x & (NQT3 - 1));  // heavy first
    int h     = (blockIdx.x >> 5) & (HH - 1);
    int b     = blockIdx.x >> 8;
    int qi    = tid >> 1;
    int half  = tid & 1;
    int t     = qtile * QT3 + qi;
    int lane  = tid & 31, wid = tid >> 5;
    int gq    = lane >> 2, tg = lane & 3;
    int qr0   = 16*wid + gq;
    unsigned pmask = 3u << (tid & 30);

    const float SCALE2 = 0.17677669529663687f * 1.4426950408889634f;  // scale*log2e

    // ---- Q fragments (A operand, 3xTF32) for this warp's 16 query rows ----
    unsigned ah[4][4], al[4][4];
    {
        int r0 = qtile * QT3 + qr0;
        const float* q0 = q + ((size_t)(b*SS + r0    )*HH + h)*DHH;
        const float* q1 = q + ((size_t)(b*SS + r0 + 8)*HH + h)*DHH;
        #pragma unroll
        for (int k8 = 0; k8 < 4; k8++) {
            float f0 = q0[k8*8 + tg    ] * SCALE2;
            float f1 = q1[k8*8 + tg    ] * SCALE2;
            float f2 = q0[k8*8 + tg + 4] * SCALE2;
            float f3 = q1[k8*8 + tg + 4] * SCALE2;
            ah[k8][0] = f2tf32(f0); al[k8][0] = f2tf32(f0 - __uint_as_float(ah[k8][0]));
            ah[k8][1] = f2tf32(f1); al[k8][1] = f2tf32(f1 - __uint_as_float(ah[k8][1]));
            ah[k8][2] = f2tf32(f2); al[k8][2] = f2tf32(f2 - __uint_as_float(ah[k8][2]));
            ah[k8][3] = f2tf32(f3); al[k8][3] = f2tf32(f3 - __uint_as_float(ah[k8][3]));
        }
    }

    int own = t >> 2;
    size_t bh_off = ((size_t)(b*HH + h))*NB*DHH;
    const float* kchb = kch + bh_off;
    const float* kclb = kcl + bh_off;
    const float* vcb  = vc  + bh_off;

    float Ml = -INFINITY, Zp = 0.f;          // Zp: this thread's partial Z
    float bval = -INFINITY; int bidx = NB;
    float oacc[4][4];                        // P.V accumulator, MMA fragment layout
    #pragma unroll
    for (int nt = 0; nt < 4; nt++)
        #pragma unroll
        for (int r = 0; r < 4; r++) oacc[nt][r] = 0.f;

    int ldrow = tid >> 3, ldc4 = tid & 7;
    size_t ldsrc = (size_t)ldrow*DHH + (ldc4 << 2);

    cp_async16(&khs[0][ldrow][ldc4 << 2], kchb + ldsrc);
    cp_async16(&kls[0][ldrow][ldc4 << 2], kclb + ldsrc);
    cp_async16(&vcs[0][ldrow][ldc4 << 2], vcb  + ldsrc);
    CP_COMMIT();
    CP_WAIT0();
    __syncthreads();

    for (int tile = 0; tile <= qtile; tile++) {
        int cur = tile & 1, nxt = cur ^ 1;
        int n0 = tile * TN;
        if (tile < qtile) {
            size_t nsrc = (size_t)(n0 + TN)*DHH + ldsrc;
            cp_async16(&khs[nxt][ldrow][ldc4 << 2], kchb + nsrc);
            cp_async16(&kls[nxt][ldrow][ldc4 << 2], kclb + nsrc);
            cp_async16(&vcs[nxt][ldrow][ldc4 << 2], vcb  + nsrc);
            CP_COMMIT();
        }

        // ---- phase A: score MMA S[64xTN] = Q . Kc^T (3xTF32) -> ss ----
        #pragma unroll
        for (int nt = 0; nt < 2; nt++) {
            float cf[4] = {0.f, 0.f, 0.f, 0.f};
            #pragma unroll
            for (int k8 = 0; k8 < 4; k8++) {
                int row = nt*8 + gq;
                int c0 = k8*8 + tg, c1 = c0 + 4;
                unsigned bh[2], bl[2];
                bh[0] = __float_as_uint(khs[cur][row][c0]);
                bh[1] = __float_as_uint(khs[cur][row][c1]);
                bl[0] = __float_as_uint(kls[cur][row][c0]);
                bl[1] = __float_as_uint(kls[cur][row][c1]);
                mma_tf32(cf, ah[k8], bh);
                mma_tf32(cf, al[k8], bh);
                mma_tf32(cf, ah[k8], bl);
            }
            int sc = nt*8 + (tg << 1);
            *(float2*)&ss[qr0    ][sc] = make_float2(cf[0], cf[1]);
            *(float2*)&ss[qr0 + 8][sc] = make_float2(cf[2], cf[3]);
        }
        __syncwarp();   // rows are warp-private

        // ---- phase B: scalar softmax bookkeeping -> P (in place), rr_s ----
        {
            int lim = (tile == qtile) ? ((qi + 1) >> 2) : TN;
            float4 sa = *(const float4*)&ss[qi][0];
            float4 sb = *(const float4*)&ss[qi][4];
            float4 sc4 = *(const float4*)&ss[qi][8];
            float4 sd = *(const float4*)&ss[qi][12];
            float s[16] = {sa.x, sa.y, sa.z, sa.w, sb.x, sb.y, sb.z, sb.w,
                           sc4.x, sc4.y, sc4.z, sc4.w, sd.x, sd.y, sd.z, sd.w};
            if (tile == qtile) {
                #pragma unroll
                for (int e = 0; e < 16; e++)
                    if (e >= lim) s[e] = -INFINITY;
            }
            #pragma unroll
            for (int e = 0; e < 16; e++) {
                int gn = n0 + e;
                if (gn != own && s[e] > bval) { bval = s[e]; bidx = gn; }
            }
            // balanced max tree
            float m0 = fmaxf(fmaxf(s[0], s[1]),  fmaxf(s[2], s[3]));
            float m1 = fmaxf(fmaxf(s[4], s[5]),  fmaxf(s[6], s[7]));
            float m2 = fmaxf(fmaxf(s[8], s[9]),  fmaxf(s[10], s[11]));
            float m3 = fmaxf(fmaxf(s[12], s[13]), fmaxf(s[14], s[15]));
            float m16 = fmaxf(fmaxf(m0, m1), fmaxf(m2, m3));
            float Mn = fmaxf(Ml, m16);
            float r = (Mn > -INFINITY) ? ex2(Ml - Mn) : 1.f;
            Zp *= r;
            Ml = Mn;
            if (half == 0) rr_s[qi] = r;
            float p[8];
            #pragma unroll
            for (int j = 0; j < 8; j++) {
                int e = (half << 3) + j;
                p[j] = (s[e] == -INFINITY) ? 0.f : ex2(s[e] - Mn);
                Zp += p[j];
            }
            *(float4*)&ss[qi][half << 3]       = make_float4(p[0], p[1], p[2], p[3]);
            *(float4*)&ss[qi][(half << 3) + 4] = make_float4(p[4], p[5], p[6], p[7]);
        }
        __syncwarp();

        // ---- phase C: P.V MMA (tf32), accumulate in fragments ----
        {
            float rA = rr_s[qr0], rB = rr_s[qr0 + 8];
            #pragma unroll
            for (int nt = 0; nt < 4; nt++) {
                oacc[nt][0] *= rA; oacc[nt][1] *= rA;
                oacc[nt][2] *= rB; oacc[nt][3] *= rB;
            }
            #pragma unroll
            for (int k8 = 0; k8 < 16; k8 += 8) {
                unsigned pa[4];
                pa[0] = f2tf32(ss[qr0    ][k8 + tg]);
                pa[1] = f2tf32(ss[qr0 + 8][k8 + tg]);
                pa[2] = f2tf32(ss[qr0    ][k8 + tg + 4]);
                pa[3] = f2tf32(ss[qr0 + 8][k8 + tg + 4]);
                #pragma unroll
                for (int nt = 0; nt < 4; nt++) {
                    unsigned vb[2];
                    vb[0] = f2tf32(vcs[cur][k8 + tg    ][nt*8 + gq]);
                    vb[1] = f2tf32(vcs[cur][k8 + tg + 4][nt*8 + gq]);
                    mma_tf32(oacc[nt], pa, vb);
                }
            }
        }

        if (tile < qtile) CP_WAIT0();
        __syncthreads();   // buffer swap + ss reuse across next score MMA
    }

    if (bval == -INFINITY) bidx = (own == 0) ? 1 : 0;

    // stage oc fragments to smem (warp-private rows)
    #pragma unroll
    for (int nt = 0; nt < 4; nt++) {
        *(float2*)&ocs[qr0    ][nt*8 + (tg << 1)] = make_float2(oacc[nt][0], oacc[nt][1]);
        *(float2*)&ocs[qr0 + 8][nt*8 + (tg << 1)] = make_float2(oacc[nt][2], oacc[nt][3]);
    }
    __syncwarp();

    // combine pair-partial Z
    float Z = Zp + __shfl_xor_sync(pmask, Zp, 1);

    // rebuild packed q (half-dh) for selection + window branches
    size_t qoff = ((size_t)(b*SS + t)*HH + h)*DHH + (half << 4);
    ull qp[8];
    {
        const float4* qr = (const float4*)(q + qoff);
        #pragma unroll
        for (int i = 0; i < 4; i++) {
            float4 f = qr[i];
            qp[2*i]   = pk2(f.x * SCALE2, f.y * SCALE2);
            qp[2*i+1] = pk2(f.z * SCALE2, f.w * SCALE2);
        }
    }

    const float* gr = g + (size_t)(b*SS + t)*24;
    float g0 = gr[h], g1 = gr[8 + h], g2 = gr[16 + h];

    // av2 = g0/Z * oc  (read this thread's dh-half from ocs)
    float invZ = (Z > 0.f) ? (1.f / Z) : 0.f;
    ull av2[8];
    {
        ull c0p = pk2(g0 * invZ, g0 * invZ);
        const ulonglong2* op = (const ulonglong2*)&ocs[qi][half << 4];
        #pragma unroll
        for (int j = 0; j < 4; j++) {
            ulonglong2 w = op[j];
            av2[2*j]   = mul2(w.x, c0p);
            av2[2*j+1] = mul2(w.y, c0p);
        }
    }

    // ---- selection branch: blocks {own, bidx}, 8 keys, mask pos<=t ----
    float sc[8];
    float smax = -INFINITY;
    #pragma unroll
    for (int e = 0; e < 8; e++) {
        int pos = ((e < 4) ? own : bidx) * 4 + (e & 3);
        const ulonglong2* kr = (const ulonglong2*)(k + ((size_t)(b*SS + pos)*HH + h)*DHH + (half << 4));
        ull acc = 0;
        #pragma unroll
        for (int i = 0; i < 4; i++) {
            ulonglong2 kk2 = kr[i];
            acc = fma2(qp[2*i], kk2.x, acc);
            acc = fma2(qp[2*i+1], kk2.y, acc);
        }
        float lo, hi; upk2(lo, hi, acc);
        float sv = lo + hi;
        sv += __shfl_xor_sync(pmask, sv, 1);
        sv = (pos <= t) ? sv : -INFINITY;
        sc[e] = sv;
        smax = fmaxf(smax, sv);
    }
    float zf = 0.f;
    #pragma unroll
    for (int e = 0; e < 8; e++) { sc[e] = ex2(sc[e] - smax); zf += sc[e]; }
    float c1 = g1 / zf;
    #pragma unroll
    for (int e = 0; e < 8; e++) {
        int pos = ((e < 4) ? own : bidx) * 4 + (e & 3);
        ull ww = pk2(sc[e] * c1, sc[e] * c1);
        const ulonglong2* vr = (const ulonglong2*)(v + ((size_t)(b*SS + pos)*HH + h)*DHH + (half << 4));
        #pragma unroll
        for (int i = 0; i < 4; i++) {
            ulonglong2 vv = vr[i];
            av2[2*i]   = fma2(ww, vv.x, av2[2*i]);
            av2[2*i+1] = fma2(ww, vv.y, av2[2*i+1]);
        }
    }

    // ---- sliding-window branch: keys {t-1, t} ----
    int tp = (t > 0) ? t - 1 : 0;
    float s1w, s0w;
    {
        const ulonglong2* kr1 = (const ulonglong2*)(k + ((size_t)(b*SS + t )*HH + h)*DHH + (half << 4));
        const ulonglong2* kr0 = (const ulonglong2*)(k + ((size_t)(b*SS + tp)*HH + h)*DHH + (half << 4));
        ull ac1 = 0, ac0 = 0;
        #pragma unroll
        for (int i = 0; i < 4; i++) {
            ulonglong2 k1 = kr1[i], k0 = kr0[i];
            ac1 = fma2(qp[2*i], k1.x, ac1); ac1 = fma2(qp[2*i+1], k1.y, ac1);
            ac0 = fma2(qp[2*i], k0.x, ac0); ac0 = fma2(qp[2*i+1], k0.y, ac0);
        }
        float lo, hi;
        upk2(lo, hi, ac1); s1w = lo + hi;
        upk2(lo, hi, ac0); s0w = lo + hi;
        s1w += __shfl_xor_sync(pmask, s1w, 1);
        s0w += __shfl_xor_sync(pmask, s0w, 1);
    }
    if (t == 0) s0w = -INFINITY;
    float wm = fmaxf(s0w, s1w);
    float p0w = ex2(s0w - wm), p1w = ex2(s1w - wm);
    float c2 = g2 / (p0w + p1w);
    {
        ull w0p = pk2(p0w * c2, p0w * c2);
        ull w1p = pk2(p1w * c2, p1w * c2);
        const ulonglong2* vr1 = (const ulonglong2*)(v + ((size_t)(b*SS + t )*HH + h)*DHH + (half << 4));
        const ulonglong2* vr0 = (const ulonglong2*)(v + ((size_t)(b*SS + tp)*HH + h)*DHH + (half << 4));
        #pragma unroll
        for (int i = 0; i < 4; i++) {
            ulonglong2 v1 = vr1[i], v0 = vr0[i];
            av2[2*i]   = fma2(w1p, v1.x, fma2(w0p, v0.x, av2[2*i]));
            av2[2*i+1] = fma2(w1p, v1.y, fma2(w0p, v0.y, av2[2*i+1]));
        }
    }

    ulonglong2* orow = (ulonglong2*)(o + qoff);
    #pragma unroll
    for (int j = 0; j < 4; j++) {
        ulonglong2 w2;
        w2.x = av2[2*j]; w2.y = av2[2*j+1];
        orow[j] = w2;
    }
}

// ---------------- host orchestration ----------------
extern "C" void kernel_launch(void* const* d_in, const int* in_sizes, int n_in,
                              void* d_out, int out_size)
{
    const float* x_in   = (const float*)d_in[0];
    const float* ln_a_g = (const float*)d_in[1];
    const float* ln_a_b = (const float*)d_in[2];
    const float* Wq     = (const float*)d_in[3];
    const float* Wk     = (const float*)d_in[4];
    const float* Wv     = (const float*)d_in[5];
    const float* Wg     = (const float*)d_in[6];
    const float* Wo     = (const float*)d_in[7];
    const float* ln_f_g = (const float*)d_in[8];
    const float* ln_f_b = (const float*)d_in[9];
    const float* W1     = (const float*)d_in[10];
    const float* b1     = (const float*)d_in[11];
    const float* W2     = (const float*)d_in[12];
    const float* b2     = (const float*)d_in[13];
    float* x = (float*)d_out;

    float *ph, *pq, *pk, *pv, *po, *pg, *pkch, *pkcl, *pvc, *pmid;
    cudaGetSymbolAddress((void**)&ph,   g_h);
    cudaGetSymbolAddress((void**)&pq,   g_q);
    cudaGetSymbolAddress((void**)&pk,   g_k);
    cudaGetSymbolAddress((void**)&pv,   g_v);
    cudaGetSymbolAddress((void**)&po,   g_o);
    cudaGetSymbolAddress((void**)&pg,   g_g);
    cudaGetSymbolAddress((void**)&pkch, g_kch);
    cudaGetSymbolAddress((void**)&pkcl, g_kcl);
    cudaGetSymbolAddress((void**)&pvc,  g_vc);
    cudaGetSymbolAddress((void**)&pmid, g_mid);

    cudaFuncSetAttribute(mma_gemm_kernel<0, true>,  cudaFuncAttributeMaxDynamicSharedMemorySize, GEMM_SMEM_BYTES);
    cudaFuncSetAttribute(mma_gemm_kernel<4, false>, cudaFuncAttributeMaxDynamicSharedMemorySize, GEMM_SMEM_BYTES);
    cudaFuncSetAttribute(mma_gemm_kernel<2, false>, cudaFuncAttributeMaxDynamicSharedMemorySize, GEMM_SMEM_BYTES);
    cudaFuncSetAttribute(mma_gemm_kernel<3, false>, cudaFuncAttributeMaxDynamicSharedMemorySize, GEMM_SMEM_BYTES);

    cudaMemcpyAsync(x, x_in, (size_t)BSD * sizeof(float), cudaMemcpyDeviceToDevice, 0);

    for (int l = 0; l < 2; l++) {
        for (int j2 = 0; j2 < 2; j2++) {
            int li = l*2 + j2;
            ln_kernel<<<BS/8, 256>>>(x, ln_a_g + li*DIMM, ln_a_b + li*DIMM, ph);
            mma_gemm_kernel<0, true><<<dim3(2, 64, 4), 256, GEMM_SMEM_BYTES>>>(
                ph,
                Wq + (size_t)li*DIMM*DIMM, Wk + (size_t)li*DIMM*DIMM,
                Wv + (size_t)li*DIMM*DIMM, Wg + (size_t)li*DIMM*24,
                nullptr, pq, pk, pv, pg, BS, DIMM, DIMM);
            pool_kernel<<<(BB*HH*NB*32)/256, 256>>>(pk, pv, pkch, pkcl, pvc);
            nsa_attn_kernel<<<BB*HH*NQT3, 128>>>(pq, pk, pv, pkch, pkcl, pvc, pg, po);
            mma_gemm_kernel<4, false><<<dim3(2, 64), 256, GEMM_SMEM_BYTES>>>(
                po, Wo + (size_t)li*DIMM*DIMM, nullptr, nullptr, nullptr,
                nullptr, x, nullptr, nullptr, nullptr, BS, DIMM, DIMM);
        }
        ln_kernel<<<BS/8, 256>>>(x, ln_f_g + l*DIMM, ln_f_b + l*DIMM, ph);
        mma_gemm_kernel<2, false><<<dim3(4, 64), 256, GEMM_SMEM_BYTES>>>(
            ph, W1 + (size_t)l*DIMM*512, nullptr, nullptr, nullptr,
            b1 + l*512, pmid, nullptr, nullptr, nullptr, BS, 512, DIMM);
        mma_gemm_kernel<3, false><<<dim3(2, 64), 256, GEMM_SMEM_BYTES>>>(
            pmid, W2 + (size_t)l*512*DIMM, nullptr, nullptr, nullptr,
            b2 + l*DIMM, x, nullptr, nullptr, nullptr, BS, DIMM, 512);
    }
}